// round 13
// baseline (speedup 1.0000x reference)
#include <cuda_runtime.h>
#include <cuda_bf16.h>
#include <cstdint>

#define D_MODEL 4096
#define N_TOK   8192

__device__ __nv_bfloat16 g_ahi[(size_t)N_TOK * D_MODEL];
__device__ __nv_bfloat16 g_alo[(size_t)N_TOK * D_MODEL];
__device__ __nv_bfloat16 g_wq [3][(size_t)D_MODEL * D_MODEL];
__device__ float         g_y  [(size_t)N_TOK * D_MODEL];
__device__ double        g_part[3072];
__device__ float         g_scale3[3];

static __device__ __forceinline__ uint32_t smem_u32(const void* p) {
    uint32_t r;
    asm("{ .reg .u64 t; cvta.to.shared.u64 t, %1; cvt.u32.u64 %0, t; }" : "=r"(r) : "l"(p));
    return r;
}
#define CP16(dst, ptr) do { \
    unsigned long long g_ = __cvta_generic_to_global((const void*)(ptr)); \
    asm volatile("cp.async.cg.shared.global [%0], [%1], 16;" :: "r"(dst), "l"(g_)); } while (0)
#define CP_COMMIT() asm volatile("cp.async.commit_group;")
#define CP_WAIT(n)  asm volatile("cp.async.wait_group %0;" :: "n"(n))

static __device__ __forceinline__ void ldsm4(uint32_t a[4], uint32_t addr) {
    asm volatile("ldmatrix.sync.aligned.m8n8.x4.shared.b16 {%0,%1,%2,%3}, [%4];"
                 : "=r"(a[0]), "=r"(a[1]), "=r"(a[2]), "=r"(a[3]) : "r"(addr));
}
static __device__ __forceinline__ void mma16816(float c[4], const uint32_t a[4], const uint32_t* b) {
    asm volatile("mma.sync.aligned.m16n8k16.row.col.f32.bf16.bf16.f32 "
                 "{%0,%1,%2,%3}, {%4,%5,%6,%7}, {%8,%9}, {%0,%1,%2,%3};"
                 : "+f"(c[0]), "+f"(c[1]), "+f"(c[2]), "+f"(c[3])
                 : "r"(a[0]), "r"(a[1]), "r"(a[2]), "r"(a[3]), "r"(b[0]), "r"(b[1]));
}

// ---- weight prologue: abs-mean (fp64) + ternarize, all 3 layers ----
__global__ void __launch_bounds__(256) absmean_part3(const float* __restrict__ w0,
                                                     const float* __restrict__ w1,
                                                     const float* __restrict__ w2) {
    int wsel = blockIdx.x >> 10;
    const float* w = (wsel == 0) ? w0 : (wsel == 1) ? w1 : w2;
    int b = blockIdx.x & 1023;
    double s = 0.0;
    for (int i = b * 256 + threadIdx.x; i < D_MODEL * D_MODEL; i += 1024 * 256)
        s += (double)fabsf(w[i]);
    __shared__ double rd[256];
    rd[threadIdx.x] = s; __syncthreads();
    for (int o = 128; o > 0; o >>= 1) { if (threadIdx.x < o) rd[threadIdx.x] += rd[threadIdx.x + o]; __syncthreads(); }
    if (threadIdx.x == 0) g_part[blockIdx.x] = rd[0];
}
__global__ void __launch_bounds__(256) absmean_fin3() {
    int t = threadIdx.x, base = blockIdx.x << 10;
    __shared__ double rd[256];
    rd[t] = g_part[base + t] + g_part[base + t + 256] + g_part[base + t + 512] + g_part[base + t + 768];
    __syncthreads();
    for (int o = 128; o > 0; o >>= 1) { if (t < o) rd[t] += rd[t + o]; __syncthreads(); }
    if (t == 0) g_scale3[blockIdx.x] = (float)(rd[0] / 16777216.0 + 1e-8);
}
__global__ void __launch_bounds__(256) quant3(const float* __restrict__ w0,
                                              const float* __restrict__ w1,
                                              const float* __restrict__ w2) {
    int wsel = blockIdx.x >> 11;
    const float* w = (wsel == 0) ? w0 : (wsel == 1) ? w1 : w2;
    __nv_bfloat162* outp = (__nv_bfloat162*)g_wq[wsel];
    const float s = g_scale3[wsel];
    int b = blockIdx.x & 2047;
    for (int i = b * 256 + threadIdx.x; i < (D_MODEL * D_MODEL) / 4; i += 2048 * 256) {
        float4 wv = ((const float4*)w)[i];
        __nv_bfloat162 a, c;
        a.x = __float2bfloat16(fminf(fmaxf(rintf(wv.x / s), -1.f), 1.f));
        a.y = __float2bfloat16(fminf(fmaxf(rintf(wv.y / s), -1.f), 1.f));
        c.x = __float2bfloat16(fminf(fmaxf(rintf(wv.z / s), -1.f), 1.f));
        c.y = __float2bfloat16(fminf(fmaxf(rintf(wv.w / s), -1.f), 1.f));
        outp[2 * i] = a;
        outp[2 * i + 1] = c;
    }
}

// ---- act: RMSNorm -> SiLU -> exact hi/lo bf16 split ----
__global__ void __launch_bounds__(256) act_kernel(const float* __restrict__ xin, int first) {
    const float* in = first ? xin : (const float*)g_y;
    int row = blockIdx.x, t = threadIdx.x;
    const float4* rp = (const float4*)(in + (size_t)row * D_MODEL);
    float4 v[4]; float ss = 0.f;
#pragma unroll
    for (int i = 0; i < 4; i++) {
        v[i] = rp[t + (i << 8)];
        ss += v[i].x * v[i].x + v[i].y * v[i].y + v[i].z * v[i].z + v[i].w * v[i].w;
    }
    __shared__ float red[256];
    red[t] = ss; __syncthreads();
#pragma unroll
    for (int o = 128; o > 0; o >>= 1) { if (t < o) red[t] += red[t + o]; __syncthreads(); }
    float rs = rsqrtf(red[0] * (1.0f / 4096.0f) + 1.1920929e-7f);
    __nv_bfloat162* hi = (__nv_bfloat162*)(g_ahi + (size_t)row * D_MODEL);
    __nv_bfloat162* lo = (__nv_bfloat162*)(g_alo + (size_t)row * D_MODEL);
#pragma unroll
    for (int i = 0; i < 4; i++) {
        float h[4] = {v[i].x * rs, v[i].y * rs, v[i].z * rs, v[i].w * rs};
        __nv_bfloat16 hh[4]; float ll[4];
#pragma unroll
        for (int e = 0; e < 4; e++) {
            h[e] = h[e] / (1.0f + expf(-h[e]));
            hh[e] = __float2bfloat16(h[e]);
            ll[e] = h[e] - __bfloat162float(hh[e]);
        }
        int base = (t + (i << 8)) * 2;
        __nv_bfloat162 p0, p1, q0, q1;
        p0.x = hh[0]; p0.y = hh[1]; p1.x = hh[2]; p1.y = hh[3];
        q0.x = __float2bfloat16(ll[0]); q0.y = __float2bfloat16(ll[1]);
        q1.x = __float2bfloat16(ll[2]); q1.y = __float2bfloat16(ll[3]);
        hi[base] = p0; hi[base + 1] = p1;
        lo[base] = q0; lo[base + 1] = q1;
    }
}

// ---- GEMM: CTA 128Mx256N, 256 thr (8 warps, warp tile 64x64), 3 stages ----
// Stage 64KB: Ahi 16K | Alo 16K | B 32K (256 rows x 128B).
#define STAGES 3
#define STAGE_BYTES 65536u
#define SMEM_TOTAL (1024 + STAGES * STAGE_BYTES)

__global__ void __launch_bounds__(256, 1) gemm_kernel(int layer, int last, float* __restrict__ dout) {
    extern __shared__ char smraw[];
    uint32_t sb = smem_u32(smraw);
    uint32_t stg = (sb + 1023u) & ~1023u;
    float* __restrict__ out = last ? dout : g_y;
    const __nv_bfloat16* __restrict__ Ahi = g_ahi;
    const __nv_bfloat16* __restrict__ Alo = g_alo;
    const __nv_bfloat16* __restrict__ Wq  = g_wq[layer];

    int tid = threadIdx.x, bid = blockIdx.x;
    int mt = ((bid >> 7) << 3) | (bid & 7);
    int nt = (bid >> 3) & 15;
    uint32_t m0 = (uint32_t)mt << 7, n0 = (uint32_t)nt << 8;

    // cp.async: A 4 chunks/thread each of hi/lo (128 rows), B 8 chunks/thread (256 rows)
    uint32_t sA[4], sB[8], gA[4], gB[8];
#pragma unroll
    for (int i = 0; i < 4; i++) {
        uint32_t q = (uint32_t)tid + ((uint32_t)i << 8), r = q >> 3, c = q & 7;
        uint32_t bo = r * 128u + c * 16u;
        sA[i] = bo ^ ((bo >> 3) & 0x70);
        gA[i] = (m0 + r) * (uint32_t)D_MODEL + c * 8u;
    }
#pragma unroll
    for (int i = 0; i < 8; i++) {
        uint32_t q = (uint32_t)tid + ((uint32_t)i << 8), r = q >> 3, c = q & 7;
        uint32_t bo = r * 128u + c * 16u;
        sB[i] = bo ^ ((bo >> 3) & 0x70);
        gB[i] = (n0 + r) * (uint32_t)D_MODEL + c * 8u;
    }
#define LOAD_STAGE(s_, kt_) do { \
    uint32_t st_ = stg + (uint32_t)(s_) * STAGE_BYTES; \
    uint32_t k0_ = (uint32_t)(kt_) * 64u; \
    _Pragma("unroll") \
    for (int i_ = 0; i_ < 4; i_++) { \
        CP16(st_ + sA[i_],           Ahi + gA[i_] + k0_); \
        CP16(st_ + 16384u + sA[i_],  Alo + gA[i_] + k0_); \
    } \
    _Pragma("unroll") \
    for (int i_ = 0; i_ < 8; i_++) CP16(st_ + 32768u + sB[i_], Wq + gB[i_] + k0_); \
} while (0)

    int wid = tid >> 5, lane = tid & 31;
    int wm = (wid & 1) << 6;   // 2 M-warps x 64
    int wn = (wid >> 1) << 6;  // 4 N-warps x 64

    float acc[4][8][4];
#pragma unroll
    for (int a = 0; a < 4; a++)
#pragma unroll
        for (int b = 0; b < 8; b++)
#pragma unroll
            for (int c = 0; c < 4; c++) acc[a][b][c] = 0.f;

    uint32_t aRow[4], aX[4], bRow[4], bX[4];
    uint32_t koffA = ((lane >> 4) & 1) * 16;
    uint32_t koffB = ((lane >> 3) & 1) * 16;
#pragma unroll
    for (int i = 0; i < 4; i++) {
        uint32_t ra = wm + i * 16 + (lane & 15);
        aRow[i] = ra * 128u; aX[i] = (ra & 7u) << 4;
        uint32_t rb = wn + i * 16 + ((lane >> 4) * 8) + (lane & 7);
        bRow[i] = rb * 128u; bX[i] = (rb & 7u) << 4;
    }

    const int KT = D_MODEL / 64;
    LOAD_STAGE(0, 0); CP_COMMIT();
    LOAD_STAGE(1, 1); CP_COMMIT();

    int s = 0;
    for (int j = 0; j < KT; j++) {
        CP_WAIT(1);
        __syncthreads();
        int jn = j + 2;
        int sl = s + 2; if (sl >= STAGES) sl -= STAGES;
        if (jn < KT) LOAD_STAGE(sl, jn);
        CP_COMMIT();

        uint32_t aB = stg + (uint32_t)s * STAGE_BYTES;
        uint32_t lB = aB + 16384u;
        uint32_t bB = aB + 32768u;
#pragma unroll
        for (int kk = 0; kk < 4; kk++) {
            uint32_t kb = kk * 32u;
            uint32_t bfr[4][4];
#pragma unroll
            for (int p = 0; p < 4; p++)
                ldsm4(bfr[p], bB + bRow[p] + ((kb + koffB) ^ bX[p]));
#pragma unroll
            for (int mi = 0; mi < 4; mi++) {
                uint32_t afr[4];
                ldsm4(afr, aB + aRow[mi] + ((kb + koffA) ^ aX[mi]));
#pragma unroll
                for (int ni = 0; ni < 8; ni++)
                    mma16816(acc[mi][ni], afr, &bfr[ni >> 1][(ni & 1) * 2]);
            }
#pragma unroll
            for (int mi = 0; mi < 4; mi++) {
                uint32_t afr[4];
                ldsm4(afr, lB + aRow[mi] + ((kb + koffA) ^ aX[mi]));
#pragma unroll
                for (int ni = 0; ni < 8; ni++)
                    mma16816(acc[mi][ni], afr, &bfr[ni >> 1][(ni & 1) * 2]);
            }
        }
        if (++s == STAGES) s = 0;
    }
    CP_WAIT(0);

    int g = lane >> 2, t4 = lane & 3;
#pragma unroll
    for (int mi = 0; mi < 4; mi++) {
        size_t r0 = (size_t)(m0 + wm + mi * 16 + g);
#pragma unroll
        for (int ni = 0; ni < 8; ni++) {
            uint32_t col = n0 + wn + ni * 8 + t4 * 2;
            *(float2*)(out + r0 * D_MODEL + col)       = make_float2(acc[mi][ni][0], acc[mi][ni][1]);
            *(float2*)(out + (r0 + 8) * D_MODEL + col) = make_float2(acc[mi][ni][2], acc[mi][ni][3]);
        }
    }
}

extern "C" void kernel_launch(void* const* d_in, const int* in_sizes, int n_in,
                              void* d_out, int out_size) {
    const float* x  = (const float*)d_in[0];
    const float* w0 = (const float*)d_in[1];
    const float* w1 = (const float*)d_in[2];
    const float* w2 = (const float*)d_in[3];
    cudaFuncSetAttribute(gemm_kernel, cudaFuncAttributeMaxDynamicSharedMemorySize, SMEM_TOTAL);
    absmean_part3<<<3072, 256>>>(w0, w1, w2);
    absmean_fin3<<<3, 256>>>();
    quant3<<<6144, 256>>>(w0, w1, w2);
    for (int l = 0; l < 3; l++) {
        act_kernel<<<N_TOK, 256>>>(x, l == 0);
        gemm_kernel<<<1024, 256, SMEM_TOTAL>>>(l, l == 2, (float*)d_out);
    }
}

// round 14
// speedup vs baseline: 1.6378x; 1.6378x over previous
#include <cuda_runtime.h>
#include <cuda_fp16.h>
#include <cstdint>

#define D_MODEL 4096
#define N_TOK   8192

__device__ __half  g_ah[(size_t)N_TOK * D_MODEL];       // fp16 activations
__device__ __half  g_wq[3][(size_t)D_MODEL * D_MODEL];  // fp16 ternary weights
__device__ float   g_y [(size_t)N_TOK * D_MODEL];       // fp32 layer output
__device__ double  g_part[3072];
__device__ float   g_scale3[3];

static __device__ __forceinline__ uint32_t smem_u32(const void* p) {
    uint32_t r;
    asm("{ .reg .u64 t; cvta.to.shared.u64 t, %1; cvt.u32.u64 %0, t; }" : "=r"(r) : "l"(p));
    return r;
}
#define CP16(dst, ptr) do { \
    unsigned long long g_ = __cvta_generic_to_global((const void*)(ptr)); \
    asm volatile("cp.async.cg.shared.global [%0], [%1], 16;" :: "r"(dst), "l"(g_)); } while (0)
#define CP_COMMIT() asm volatile("cp.async.commit_group;")
#define CP_WAIT(n)  asm volatile("cp.async.wait_group %0;" :: "n"(n))

static __device__ __forceinline__ void ldsm4(uint32_t a[4], uint32_t addr) {
    asm volatile("ldmatrix.sync.aligned.m8n8.x4.shared.b16 {%0,%1,%2,%3}, [%4];"
                 : "=r"(a[0]), "=r"(a[1]), "=r"(a[2]), "=r"(a[3]) : "r"(addr));
}
static __device__ __forceinline__ void mma16816(float c[4], const uint32_t a[4], const uint32_t* b) {
    asm volatile("mma.sync.aligned.m16n8k16.row.col.f32.f16.f16.f32 "
                 "{%0,%1,%2,%3}, {%4,%5,%6,%7}, {%8,%9}, {%0,%1,%2,%3};"
                 : "+f"(c[0]), "+f"(c[1]), "+f"(c[2]), "+f"(c[3])
                 : "r"(a[0]), "r"(a[1]), "r"(a[2]), "r"(a[3]), "r"(b[0]), "r"(b[1]));
}

// ---- weight prologue: abs-mean (fp64) + ternarize -> fp16, all 3 layers ----
__global__ void __launch_bounds__(256) absmean_part3(const float* __restrict__ w0,
                                                     const float* __restrict__ w1,
                                                     const float* __restrict__ w2) {
    int wsel = blockIdx.x >> 10;
    const float* w = (wsel == 0) ? w0 : (wsel == 1) ? w1 : w2;
    int b = blockIdx.x & 1023;
    double s = 0.0;
    for (int i = b * 256 + threadIdx.x; i < D_MODEL * D_MODEL; i += 1024 * 256)
        s += (double)fabsf(w[i]);
    __shared__ double rd[256];
    rd[threadIdx.x] = s; __syncthreads();
    for (int o = 128; o > 0; o >>= 1) { if (threadIdx.x < o) rd[threadIdx.x] += rd[threadIdx.x + o]; __syncthreads(); }
    if (threadIdx.x == 0) g_part[blockIdx.x] = rd[0];
}
__global__ void __launch_bounds__(256) absmean_fin3() {
    int t = threadIdx.x, base = blockIdx.x << 10;
    __shared__ double rd[256];
    rd[t] = g_part[base + t] + g_part[base + t + 256] + g_part[base + t + 512] + g_part[base + t + 768];
    __syncthreads();
    for (int o = 128; o > 0; o >>= 1) { if (t < o) rd[t] += rd[t + o]; __syncthreads(); }
    if (t == 0) g_scale3[blockIdx.x] = (float)(rd[0] / 16777216.0 + 1e-8);
}
__global__ void __launch_bounds__(256) quant3(const float* __restrict__ w0,
                                              const float* __restrict__ w1,
                                              const float* __restrict__ w2) {
    int wsel = blockIdx.x >> 11;
    const float* w = (wsel == 0) ? w0 : (wsel == 1) ? w1 : w2;
    __half2* outp = (__half2*)g_wq[wsel];
    const float s = g_scale3[wsel];
    int b = blockIdx.x & 2047;
    for (int i = b * 256 + threadIdx.x; i < (D_MODEL * D_MODEL) / 4; i += 2048 * 256) {
        float4 wv = ((const float4*)w)[i];
        __half2 a, c;
        a.x = __float2half_rn(fminf(fmaxf(rintf(wv.x / s), -1.f), 1.f));
        a.y = __float2half_rn(fminf(fmaxf(rintf(wv.y / s), -1.f), 1.f));
        c.x = __float2half_rn(fminf(fmaxf(rintf(wv.z / s), -1.f), 1.f));
        c.y = __float2half_rn(fminf(fmaxf(rintf(wv.w / s), -1.f), 1.f));
        outp[2 * i] = a;
        outp[2 * i + 1] = c;
    }
}

// ---- act: RMSNorm -> SiLU -> fp16 (R4 verbatim) ----
__global__ void __launch_bounds__(256) act_kernel(const float* __restrict__ xin, int first) {
    const float* in = first ? xin : (const float*)g_y;
    int row = blockIdx.x, t = threadIdx.x;
    const float4* rp = (const float4*)(in + (size_t)row * D_MODEL);
    float4 v[4]; float ss = 0.f;
#pragma unroll
    for (int i = 0; i < 4; i++) {
        v[i] = rp[t + (i << 8)];
        ss += v[i].x * v[i].x + v[i].y * v[i].y + v[i].z * v[i].z + v[i].w * v[i].w;
    }
    __shared__ float red[256];
    red[t] = ss; __syncthreads();
#pragma unroll
    for (int o = 128; o > 0; o >>= 1) { if (t < o) red[t] += red[t + o]; __syncthreads(); }
    float rs = rsqrtf(red[0] * (1.0f / 4096.0f) + 1.1920929e-7f);
    __half2* hp = (__half2*)(g_ah + (size_t)row * D_MODEL);
#pragma unroll
    for (int i = 0; i < 4; i++) {
        float h[4] = {v[i].x * rs, v[i].y * rs, v[i].z * rs, v[i].w * rs};
#pragma unroll
        for (int e = 0; e < 4; e++) h[e] = h[e] / (1.0f + expf(-h[e]));
        int base = (t + (i << 8)) * 2;
        __half2 p0, p1;
        p0.x = __float2half_rn(h[0]); p0.y = __float2half_rn(h[1]);
        p1.x = __float2half_rn(h[2]); p1.y = __float2half_rn(h[3]);
        hp[base] = p0; hp[base + 1] = p1;
    }
}

// ---- GEMM (R4 verbatim): CTA 256Mx128N, 256 thr, warp tile 64x64, 4 stages ----
#define STAGES 4
#define A_BYTES 32768u
#define B_BYTES 16384u
#define STAGE_BYTES (A_BYTES + B_BYTES)
#define SMEM_TOTAL (1024 + STAGES * STAGE_BYTES)

__global__ void __launch_bounds__(256, 1) gemm_kernel(int layer, int last, float* __restrict__ dout) {
    extern __shared__ char smraw[];
    uint32_t sb = smem_u32(smraw);
    uint32_t stg = (sb + 1023u) & ~1023u;
    float* __restrict__ out = last ? dout : g_y;
    const __half* __restrict__ Wq = g_wq[layer];

    int tid = threadIdx.x, bid = blockIdx.x;
    int mt = ((bid >> 8) << 3) | (bid & 7);
    int nt = (bid >> 3) & 31;
    int m0 = mt << 8, n0 = nt << 7;

    uint32_t sA[8], sB[4]; size_t gA[8], gB[4];
#pragma unroll
    for (int i = 0; i < 8; i++) {
        int q = tid + (i << 8), r = q >> 3, c = q & 7;
        uint32_t bo = (uint32_t)(r * 128 + c * 16);
        sA[i] = bo ^ ((bo >> 3) & 0x70);
        gA[i] = (size_t)(m0 + r) * D_MODEL + c * 8;
    }
#pragma unroll
    for (int i = 0; i < 4; i++) {
        int q = tid + (i << 8), r = q >> 3, c = q & 7;
        uint32_t bo = (uint32_t)(r * 128 + c * 16);
        sB[i] = bo ^ ((bo >> 3) & 0x70);
        gB[i] = (size_t)(n0 + r) * D_MODEL + c * 8;
    }
#define LOAD_STAGE(s_, kt_) do { \
    uint32_t st_ = stg + (uint32_t)(s_) * STAGE_BYTES; \
    size_t k0_ = (size_t)(kt_) * 64; \
    _Pragma("unroll") \
    for (int i_ = 0; i_ < 8; i_++) CP16(st_ + sA[i_], g_ah + gA[i_] + k0_); \
    _Pragma("unroll") \
    for (int i_ = 0; i_ < 4; i_++) CP16(st_ + A_BYTES + sB[i_], Wq + gB[i_] + k0_); \
} while (0)

    int wid = tid >> 5, lane = tid & 31;
    int wm = (wid & 3) << 6;
    int wn = (wid >> 2) << 6;

    float acc[4][8][4];
#pragma unroll
    for (int a = 0; a < 4; a++)
#pragma unroll
        for (int b = 0; b < 8; b++)
#pragma unroll
            for (int c = 0; c < 4; c++) acc[a][b][c] = 0.f;

    uint32_t aRow[4], aX[4], bRow[4], bX[4];
    uint32_t koffA = ((lane >> 4) & 1) * 16;
    uint32_t koffB = ((lane >> 3) & 1) * 16;
#pragma unroll
    for (int i = 0; i < 4; i++) {
        uint32_t ra = wm + i * 16 + (lane & 15);
        aRow[i] = ra * 128u; aX[i] = (ra & 7u) << 4;
        uint32_t rb = wn + i * 16 + ((lane >> 4) * 8) + (lane & 7);
        bRow[i] = rb * 128u; bX[i] = (rb & 7u) << 4;
    }

    const int KT = D_MODEL / 64;
    for (int j = 0; j < STAGES - 1; j++) { LOAD_STAGE(j, j); CP_COMMIT(); }

    for (int j = 0; j < KT; j++) {
        int s = j & 3;
        CP_WAIT(2);
        __syncthreads();
        uint32_t aB = stg + (uint32_t)s * STAGE_BYTES;
        uint32_t bB = aB + A_BYTES;
#pragma unroll
        for (int kk = 0; kk < 4; kk++) {
            uint32_t kb = kk * 32u;
            uint32_t bfr[4][4];
#pragma unroll
            for (int p = 0; p < 4; p++)
                ldsm4(bfr[p], bB + bRow[p] + ((kb + koffB) ^ bX[p]));
#pragma unroll
            for (int mt2 = 0; mt2 < 4; mt2++) {
                uint32_t afr[4];
                ldsm4(afr, aB + aRow[mt2] + ((kb + koffA) ^ aX[mt2]));
#pragma unroll
                for (int nt2 = 0; nt2 < 8; nt2++)
                    mma16816(acc[mt2][nt2], afr, &bfr[nt2 >> 1][(nt2 & 1) * 2]);
            }
        }
        __syncthreads();
        int jn = j + STAGES - 1;
        if (jn < KT) { int sn = jn & 3; LOAD_STAGE(sn, jn); }
        CP_COMMIT();
    }
    CP_WAIT(0);

    int g = lane >> 2, t4 = lane & 3;
#pragma unroll
    for (int mt2 = 0; mt2 < 4; mt2++) {
        size_t r0 = (size_t)(m0 + wm + mt2 * 16 + g);
#pragma unroll
        for (int nt2 = 0; nt2 < 8; nt2++) {
            int col = n0 + wn + nt2 * 8 + t4 * 2;
            *(float2*)(out + r0 * D_MODEL + col)       = make_float2(acc[mt2][nt2][0], acc[mt2][nt2][1]);
            *(float2*)(out + (r0 + 8) * D_MODEL + col) = make_float2(acc[mt2][nt2][2], acc[mt2][nt2][3]);
        }
    }
}

extern "C" void kernel_launch(void* const* d_in, const int* in_sizes, int n_in,
                              void* d_out, int out_size) {
    const float* x  = (const float*)d_in[0];
    const float* w0 = (const float*)d_in[1];
    const float* w1 = (const float*)d_in[2];
    const float* w2 = (const float*)d_in[3];
    cudaFuncSetAttribute(gemm_kernel, cudaFuncAttributeMaxDynamicSharedMemorySize, SMEM_TOTAL);
    absmean_part3<<<3072, 256>>>(w0, w1, w2);
    absmean_fin3<<<3, 256>>>();
    quant3<<<6144, 256>>>(w0, w1, w2);
    for (int l = 0; l < 3; l++) {
        act_kernel<<<N_TOK, 256>>>(x, l == 0);
        gemm_kernel<<<1024, 256, SMEM_TOTAL>>>(l, l == 2, (float*)d_out);
    }
}